// round 7
// baseline (speedup 1.0000x reference)
#include <cuda_runtime.h>
#include <cstddef>

// Problem constants (fixed by the dataset)
#define DD 16     // ds_dim
#define NN 32     // number of systems
#define HH 128    // gating hidden width
#define THREADS 416
#define RPT 2     // rows per thread

typedef unsigned long long ull;

// ---- f32x2 packed-math helpers (sm_103a) ----
__device__ __forceinline__ ull pack2(float lo, float hi) {
    ull r; asm("mov.b64 %0, {%1,%2};" : "=l"(r) : "f"(lo), "f"(hi)); return r;
}
__device__ __forceinline__ ull dup2(float v) { return pack2(v, v); }
__device__ __forceinline__ void unpack2(ull v, float& lo, float& hi) {
    asm("mov.b64 {%0,%1}, %2;" : "=f"(lo), "=f"(hi) : "l"(v));
}
__device__ __forceinline__ ull fma2(ull a, ull b, ull c) {
    ull d; asm("fma.rn.f32x2 %0, %1, %2, %3;" : "=l"(d) : "l"(a), "l"(b), "l"(c));
    return d;
}
__device__ __forceinline__ ull add2(ull a, ull b) {
    ull d; asm("add.rn.f32x2 %0, %1, %2;" : "=l"(d) : "l"(a), "l"(b)); return d;
}
__device__ __forceinline__ ull mul2(ull a, ull b) {
    ull d; asm("mul.rn.f32x2 %0, %1, %2;" : "=l"(d) : "l"(a), "l"(b)); return d;
}

// Dynamic smem layout (floats):
//   sW1n [H*D]    -W1[j][d] row-major (d-pairs feed fma2 with diffp)
//   sW2t [H*N]    transposed: sW2t[j*N + n] = W2[n*H + j]
//   sA   [N*D*D]  A = B+C in ORIGINAL [n][k][d] layout (d contiguous)
//   sb1p [H]      b1'[j] = b1[j] + sum_d W1[j][d]*xt[d]
//   sb2  [N], sxt [D]
//   swb  [N*RPT*THREADS]  per-thread normalized softmax weights
#define W_FLOATS (HH*DD + HH*NN + NN*DD*DD + HH + NN + DD)
#define SMEM_FLOATS (W_FLOATS + NN*RPT*THREADS)

__global__ __launch_bounds__(THREADS)
void fused_gated_ds_kernel(
    const float* __restrict__ x_cur,
    const float* __restrict__ W1,
    const float* __restrict__ b1,
    const float* __restrict__ W2,
    const float* __restrict__ b2,
    const float* __restrict__ Bm,
    const float* __restrict__ Cm,
    const float* __restrict__ xt,
    float* __restrict__ out,
    int Btot)
{
    extern __shared__ float smem[];
    float* sW1n = smem;                    // 2048
    float* sW2t = sW1n + HH*DD;            // 4096
    float* sA   = sW2t + HH*NN;            // 8192
    float* sb1p = sA   + NN*DD*DD;         // 128
    float* sb2  = sb1p + HH;               // 32
    float* sxt  = sb2  + NN;               // 16
    float* swb  = smem + W_FLOATS;

    const int tid = threadIdx.x;

    // ---- stage weights ----
    for (int i = tid; i < HH*DD; i += THREADS) sW1n[i] = -W1[i];
    for (int i = tid; i < HH*NN; i += THREADS) {
        int j = i / NN, n = i % NN;
        sW2t[i] = W2[n*HH + j];
    }
    for (int i = tid; i < NN*DD*DD; i += THREADS) sA[i] = Bm[i] + Cm[i];
    if (tid < NN) sb2[tid] = b2[tid];
    if (tid < DD) sxt[tid] = xt[tid];
    __syncthreads();

    // b1'[j] = b1[j] + sum_d W1[j][d]*xt[d]
    if (tid < HH) {
        float s = b1[tid];
        #pragma unroll
        for (int d = 0; d < DD; d++) s += W1[tid*DD + d] * sxt[d];
        sb1p[tid] = s;
    }
    __syncthreads();

    const int base = blockIdx.x * (THREADS * RPT);
    const int r0 = base + tid;
    const int r1 = base + THREADS + tid;
    if (r0 >= Btot) return;
    const bool act1 = (r1 < Btot);

    // ---- diffp[r][dp] = {xt-x} packed over d-pairs (only x-derived state) ----
    ull diffp[RPT][8];
    {
        const float4* xg = reinterpret_cast<const float4*>(x_cur + (size_t)r0 * DD);
        #pragma unroll
        for (int q = 0; q < 4; q++) {
            float4 v = xg[q];
            diffp[0][2*q]   = pack2(sxt[4*q+0] - v.x, sxt[4*q+1] - v.y);
            diffp[0][2*q+1] = pack2(sxt[4*q+2] - v.z, sxt[4*q+3] - v.w);
        }
    }
    if (act1) {
        const float4* xg = reinterpret_cast<const float4*>(x_cur + (size_t)r1 * DD);
        #pragma unroll
        for (int q = 0; q < 4; q++) {
            float4 v = xg[q];
            diffp[1][2*q]   = pack2(sxt[4*q+0] - v.x, sxt[4*q+1] - v.y);
            diffp[1][2*q+1] = pack2(sxt[4*q+2] - v.z, sxt[4*q+3] - v.w);
        }
    } else {
        #pragma unroll
        for (int i = 0; i < 8; i++) diffp[1][i] = 0ULL;
    }

    // ---- logits packed over n-pairs ----
    ull Lp[RPT][16];
    {
        const ulonglong2* b2p = reinterpret_cast<const ulonglong2*>(sb2);
        #pragma unroll
        for (int q = 0; q < 8; q++) {
            ulonglong2 v = b2p[q];
            Lp[0][2*q] = v.x; Lp[0][2*q+1] = v.y;
            Lp[1][2*q] = v.x; Lp[1][2*q+1] = v.y;
        }
    }

    // ---- fused GEMM1 (on diff, bias-folded, relu) + GEMM2 ----
    #pragma unroll 2
    for (int j = 0; j < HH; j++) {
        const ulonglong2* w1p = reinterpret_cast<const ulonglong2*>(sW1n + j*DD);
        ulonglong2 wA = w1p[0], wB = w1p[1], wC = w1p[2], wD = w1p[3];
        const float bj = sb1p[j];
        ull hd[RPT];
        #pragma unroll
        for (int r = 0; r < RPT; r++) {
            ull s0 = fma2(wA.x, diffp[r][0], 0ULL);
            ull s1 = fma2(wA.y, diffp[r][1], 0ULL);
            s0 = fma2(wB.x, diffp[r][2], s0);
            s1 = fma2(wB.y, diffp[r][3], s1);
            s0 = fma2(wC.x, diffp[r][4], s0);
            s1 = fma2(wC.y, diffp[r][5], s1);
            s0 = fma2(wD.x, diffp[r][6], s0);
            s1 = fma2(wD.y, diffp[r][7], s1);
            ull s = add2(s0, s1);
            float lo, hi; unpack2(s, lo, hi);
            hd[r] = dup2(fmaxf(lo + hi + bj, 0.0f));
        }
        const ulonglong2* w2p = reinterpret_cast<const ulonglong2*>(sW2t + j*NN);
        #pragma unroll
        for (int q = 0; q < 8; q++) {
            ulonglong2 wv = w2p[q];
            #pragma unroll
            for (int r = 0; r < RPT; r++) {
                Lp[r][2*q]   = fma2(wv.x, hd[r], Lp[r][2*q]);
                Lp[r][2*q+1] = fma2(wv.y, hd[r], Lp[r][2*q+1]);
            }
        }
    }

    // ---- softmax per row; store normalized weights (Lp dies) ----
    #pragma unroll
    for (int r = 0; r < RPT; r++) {
        float ev[NN];
        #pragma unroll
        for (int i = 0; i < 16; i++) unpack2(Lp[r][i], ev[2*i], ev[2*i+1]);
        float m = ev[0];
        #pragma unroll
        for (int n = 1; n < NN; n++) m = fmaxf(m, ev[n]);
        float s = 0.0f;
        #pragma unroll
        for (int n = 0; n < NN; n++) { ev[n] = __expf(ev[n] - m); s += ev[n]; }
        const float inv = 1.0f / s;
        #pragma unroll
        for (int n = 0; n < NN; n++) swb[(n*RPT + r)*THREADS + tid] = ev[n] * inv;
    }

    // ---- epilogue, packed over d, two k-passes (k 0..7, 8..15) ----
    // outpair[r][kk] accumulates {sum over even d, sum over odd d}
    #pragma unroll
    for (int pass = 0; pass < 2; pass++) {
        const int k0 = pass * 8;
        ull outpair[RPT][8];
        #pragma unroll
        for (int r = 0; r < RPT; r++)
            #pragma unroll
            for (int kk = 0; kk < 8; kk++) outpair[r][kk] = 0ULL;

        #pragma unroll 1
        for (int n = 0; n < NN; n++) {
            // per-n scaled diff: zp = w_n * diffp
            ull zp[RPT][8];
            #pragma unroll
            for (int r = 0; r < RPT; r++) {
                const ull wd = dup2(swb[(n*RPT + r)*THREADS + tid]);
                #pragma unroll
                for (int dp = 0; dp < 8; dp++)
                    zp[r][dp] = mul2(wd, diffp[r][dp]);
            }
            const ulonglong2* ap =
                reinterpret_cast<const ulonglong2*>(sA + n*DD*DD + k0*DD);
            #pragma unroll
            for (int kk = 0; kk < 8; kk++) {
                ulonglong2 a0 = ap[4*kk + 0];   // d-pairs 0,1
                ulonglong2 a1 = ap[4*kk + 1];   // d-pairs 2,3
                ulonglong2 a2 = ap[4*kk + 2];   // d-pairs 4,5
                ulonglong2 a3 = ap[4*kk + 3];   // d-pairs 6,7
                #pragma unroll
                for (int r = 0; r < RPT; r++) {
                    ull acc = outpair[r][kk];
                    acc = fma2(a0.x, zp[r][0], acc);
                    acc = fma2(a0.y, zp[r][1], acc);
                    acc = fma2(a1.x, zp[r][2], acc);
                    acc = fma2(a1.y, zp[r][3], acc);
                    acc = fma2(a2.x, zp[r][4], acc);
                    acc = fma2(a2.y, zp[r][5], acc);
                    acc = fma2(a3.x, zp[r][6], acc);
                    acc = fma2(a3.y, zp[r][7], acc);
                    outpair[r][kk] = acc;
                }
            }
        }

        // horizontal add + store this pass's 8 outputs per row
        {
            float o[8];
            #pragma unroll
            for (int kk = 0; kk < 8; kk++) {
                float lo, hi; unpack2(outpair[0][kk], lo, hi);
                o[kk] = lo + hi;
            }
            float4* og = reinterpret_cast<float4*>(out + (size_t)r0 * DD + k0);
            og[0] = make_float4(o[0], o[1], o[2], o[3]);
            og[1] = make_float4(o[4], o[5], o[6], o[7]);
        }
        if (act1) {
            float o[8];
            #pragma unroll
            for (int kk = 0; kk < 8; kk++) {
                float lo, hi; unpack2(outpair[1][kk], lo, hi);
                o[kk] = lo + hi;
            }
            float4* og = reinterpret_cast<float4*>(out + (size_t)r1 * DD + k0);
            og[0] = make_float4(o[0], o[1], o[2], o[3]);
            og[1] = make_float4(o[4], o[5], o[6], o[7]);
        }
    }
}

extern "C" void kernel_launch(void* const* d_in, const int* in_sizes, int n_in,
                              void* d_out, int out_size)
{
    const float* x_cur = (const float*)d_in[0];
    const float* W1    = (const float*)d_in[1];
    const float* b1    = (const float*)d_in[2];
    const float* W2    = (const float*)d_in[3];
    const float* b2    = (const float*)d_in[4];
    const float* Bm    = (const float*)d_in[5];
    const float* Cm    = (const float*)d_in[6];
    const float* xt    = (const float*)d_in[7];
    float* out = (float*)d_out;

    const int Btot = in_sizes[0] / DD;
    const size_t smem_bytes = (size_t)SMEM_FLOATS * sizeof(float);

    cudaFuncSetAttribute(fused_gated_ds_kernel,
                         cudaFuncAttributeMaxDynamicSharedMemorySize,
                         (int)smem_bytes);

    const int rows_per_cta = THREADS * RPT;
    const int grid = (Btot + rows_per_cta - 1) / rows_per_cta;
    fused_gated_ds_kernel<<<grid, THREADS, smem_bytes>>>(
        x_cur, W1, b1, W2, b2, Bm, Cm, xt, out, Btot);
}

// round 11
// speedup vs baseline: 3.4767x; 3.4767x over previous
#include <cuda_runtime.h>
#include <cstdint>

#define DD 16
#define NN 32
#define HH 128
#define TMROWS 128
#define THREADS 256
#define WARPS 8

// smem float-index offsets (padded strides for conflict-free fragment LDS)
#define OF_XT    0
#define OF_B2    16
#define OF_B1P   48
#define OF_W1    176
#define W1_STR   20                          /* [128][20] */
#define OF_W2    (OF_W1 + HH*W1_STR)         /* 2736 */
#define W2_STR   132                         /* [32][132] */
#define OF_F     (OF_W2 + NN*W2_STR)         /* 6960 */
#define F_STR    516                         /* [16][516] */
#define OF_DIFF  (OF_F + DD*F_STR)           /* 15216 */
#define DF_STR   20                          /* [128][20] */
#define OF_H     (OF_DIFF + TMROWS*DF_STR)   /* 17776 */
#define H_STR    132                         /* per warp [16][132] */
#define OF_WB    (OF_H + WARPS*16*H_STR)     /* 34672 */
#define WB_STR   36                          /* per warp [16][36] */
#define SMEM_FLOATS (OF_WB + WARPS*16*WB_STR)
#define SMEM_BYTES  (SMEM_FLOATS*4)

__device__ __forceinline__ uint32_t tf32u(float x) {
    uint32_t u; asm("cvt.rna.tf32.f32 %0, %1;" : "=r"(u) : "f"(x)); return u;
}
__device__ __forceinline__ float tf32f(float x) {
    uint32_t u; asm("cvt.rna.tf32.f32 %0, %1;" : "=r"(u) : "f"(x)); return __uint_as_float(u);
}
__device__ __forceinline__ void mma8(float& c0, float& c1, float& c2, float& c3,
                                     uint32_t a0, uint32_t a1, uint32_t a2, uint32_t a3,
                                     uint32_t b0, uint32_t b1) {
    asm("mma.sync.aligned.m16n8k8.row.col.f32.tf32.tf32.f32 "
        "{%0,%1,%2,%3},{%4,%5,%6,%7},{%8,%9},{%0,%1,%2,%3};"
        : "+f"(c0), "+f"(c1), "+f"(c2), "+f"(c3)
        : "r"(a0), "r"(a1), "r"(a2), "r"(a3), "r"(b0), "r"(b1));
}

__global__ __launch_bounds__(THREADS, 1)
void fused_gated_ds_mma(
    const float* __restrict__ x_cur,
    const float* __restrict__ W1,
    const float* __restrict__ b1,
    const float* __restrict__ W2,
    const float* __restrict__ b2,
    const float* __restrict__ Bm,
    const float* __restrict__ Cm,
    const float* __restrict__ xt,
    float* __restrict__ out,
    int Btot, int ntiles)
{
    extern __shared__ float sm[];
    uint32_t* smu = (uint32_t*)sm;

    const int tid  = threadIdx.x;
    const int warp = tid >> 5;
    const int lane = tid & 31;
    const int g    = lane >> 2;   // groupID (row within m16 half)
    const int tig  = lane & 3;    // thread-in-group

    // ---- stage small vectors ----
    if (tid < DD) sm[OF_XT + tid] = xt[tid];
    if (tid < NN) sm[OF_B2 + tid] = b2[tid];
    __syncthreads();

    // ---- stage weights (once; persistent CTA) ----
    for (int i = tid; i < HH*DD; i += THREADS) {          // W1 [j][d] -> [j][20]
        int j = i >> 4, d = i & 15;
        sm[OF_W1 + j*W1_STR + d] = tf32f(W1[i]);
    }
    for (int i = tid; i < NN*HH; i += THREADS) {          // W2 [n][j] -> [n][132]
        int n = i >> 7, j = i & 127;
        sm[OF_W2 + n*W2_STR + j] = tf32f(W2[i]);
    }
    for (int i = tid; i < DD*NN*DD; i += THREADS) {       // F [k][q], q=n*16+d
        int k = i >> 9, q = i & 511;
        int n = q >> 4, d = q & 15;
        int src = n*256 + k*16 + d;
        sm[OF_F + k*F_STR + q] = tf32f(Bm[src] + Cm[src]);
    }
    if (tid < HH) {                                        // b1'[j] = b1[j] + W1 xt
        float s = b1[tid];
        #pragma unroll
        for (int d = 0; d < DD; d++) s += W1[tid*DD + d] * sm[OF_XT + d];
        sm[OF_B1P + tid] = s;
    }
    __syncthreads();

    const int wrb = warp * 16;
    float* sH  = sm + OF_H  + warp*16*H_STR;
    float* sWb = sm + OF_WB + warp*16*WB_STR;
    uint32_t* sHu = (uint32_t*)sH;

    for (int tile = blockIdx.x; tile < ntiles; tile += gridDim.x) {
        // ---- stage diff tile [128][20] (fp32): diff = xt - x ----
        {
            const int r  = tid >> 1;
            const int h8 = (tid & 1) * 8;
            const int row = tile*TMROWS + r;
            float4 d0 = make_float4(0.f,0.f,0.f,0.f), d1 = d0;
            if (row < Btot) {
                const float4* xg = (const float4*)(x_cur + (size_t)row*DD + h8);
                float4 v0 = xg[0], v1 = xg[1];
                d0.x = sm[OF_XT+h8+0] - v0.x; d0.y = sm[OF_XT+h8+1] - v0.y;
                d0.z = sm[OF_XT+h8+2] - v0.z; d0.w = sm[OF_XT+h8+3] - v0.w;
                d1.x = sm[OF_XT+h8+4] - v1.x; d1.y = sm[OF_XT+h8+5] - v1.y;
                d1.z = sm[OF_XT+h8+6] - v1.z; d1.w = sm[OF_XT+h8+7] - v1.w;
            }
            *(float4*)(sm + OF_DIFF + r*DF_STR + h8)     = d0;
            *(float4*)(sm + OF_DIFF + r*DF_STR + h8 + 4) = d1;
        }
        __syncthreads();

        // ================= G1: D1[16x128] = diff[16x16] @ W1^T =================
        uint32_t af[2][4];
        #pragma unroll
        for (int ks = 0; ks < 2; ks++) {
            af[ks][0] = tf32u(sm[OF_DIFF + (wrb+g  )*DF_STR + ks*8 + tig    ]);
            af[ks][1] = tf32u(sm[OF_DIFF + (wrb+g+8)*DF_STR + ks*8 + tig    ]);
            af[ks][2] = tf32u(sm[OF_DIFF + (wrb+g  )*DF_STR + ks*8 + tig + 4]);
            af[ks][3] = tf32u(sm[OF_DIFF + (wrb+g+8)*DF_STR + ks*8 + tig + 4]);
        }
        float acc1[16][4];
        #pragma unroll
        for (int nt = 0; nt < 16; nt++)
            acc1[nt][0] = acc1[nt][1] = acc1[nt][2] = acc1[nt][3] = 0.f;
        #pragma unroll
        for (int ks = 0; ks < 2; ks++) {
            #pragma unroll
            for (int nt = 0; nt < 16; nt++) {
                uint32_t b0 = smu[OF_W1 + (nt*8+g)*W1_STR + ks*8 + tig];
                uint32_t b1v = smu[OF_W1 + (nt*8+g)*W1_STR + ks*8 + tig + 4];
                mma8(acc1[nt][0], acc1[nt][1], acc1[nt][2], acc1[nt][3],
                     af[ks][0], af[ks][1], af[ks][2], af[ks][3], b0, b1v);
            }
        }

        // ---- H = relu(b1' - D1) -> per-warp smem (tf32) ----
        #pragma unroll
        for (int nt = 0; nt < 16; nt++) {
            int c0 = nt*8 + 2*tig;
            float2 bb = *(float2*)(sm + OF_B1P + c0);
            float2 h0, h1;
            h0.x = tf32f(fmaxf(bb.x - acc1[nt][0], 0.f));
            h0.y = tf32f(fmaxf(bb.y - acc1[nt][1], 0.f));
            h1.x = tf32f(fmaxf(bb.x - acc1[nt][2], 0.f));
            h1.y = tf32f(fmaxf(bb.y - acc1[nt][3], 0.f));
            *(float2*)(sH + (g  )*H_STR + c0) = h0;
            *(float2*)(sH + (g+8)*H_STR + c0) = h1;
        }
        __syncwarp();

        // ================= G2: L[16x32] = H[16x128] @ W2^T =================
        float acc2[4][4];
        #pragma unroll
        for (int nt = 0; nt < 4; nt++)
            acc2[nt][0] = acc2[nt][1] = acc2[nt][2] = acc2[nt][3] = 0.f;
        #pragma unroll 4
        for (int kt = 0; kt < 16; kt++) {
            uint32_t a0 = sHu[(g  )*H_STR + kt*8 + tig];
            uint32_t a1 = sHu[(g+8)*H_STR + kt*8 + tig];
            uint32_t a2 = sHu[(g  )*H_STR + kt*8 + tig + 4];
            uint32_t a3 = sHu[(g+8)*H_STR + kt*8 + tig + 4];
            #pragma unroll
            for (int nt = 0; nt < 4; nt++) {
                uint32_t b0 = smu[OF_W2 + (nt*8+g)*W2_STR + kt*8 + tig];
                uint32_t b1v = smu[OF_W2 + (nt*8+g)*W2_STR + kt*8 + tig + 4];
                mma8(acc2[nt][0], acc2[nt][1], acc2[nt][2], acc2[nt][3],
                     a0, a1, a2, a3, b0, b1v);
            }
        }

        // ---- softmax (rows g and g+8; logits of a row live in one quad) ----
        {
            float l0[8], l1[8];
            #pragma unroll
            for (int nt = 0; nt < 4; nt++) {
                float2 bv = *(float2*)(sm + OF_B2 + nt*8 + 2*tig);
                l0[2*nt]   = acc2[nt][0] + bv.x;  l0[2*nt+1] = acc2[nt][1] + bv.y;
                l1[2*nt]   = acc2[nt][2] + bv.x;  l1[2*nt+1] = acc2[nt][3] + bv.y;
            }
            float m0 = l0[0], m1 = l1[0];
            #pragma unroll
            for (int i = 1; i < 8; i++) { m0 = fmaxf(m0, l0[i]); m1 = fmaxf(m1, l1[i]); }
            m0 = fmaxf(m0, __shfl_xor_sync(0xffffffffu, m0, 1));
            m0 = fmaxf(m0, __shfl_xor_sync(0xffffffffu, m0, 2));
            m1 = fmaxf(m1, __shfl_xor_sync(0xffffffffu, m1, 1));
            m1 = fmaxf(m1, __shfl_xor_sync(0xffffffffu, m1, 2));
            float s0 = 0.f, s1 = 0.f;
            #pragma unroll
            for (int i = 0; i < 8; i++) {
                l0[i] = __expf(l0[i] - m0); s0 += l0[i];
                l1[i] = __expf(l1[i] - m1); s1 += l1[i];
            }
            s0 += __shfl_xor_sync(0xffffffffu, s0, 1);
            s0 += __shfl_xor_sync(0xffffffffu, s0, 2);
            s1 += __shfl_xor_sync(0xffffffffu, s1, 1);
            s1 += __shfl_xor_sync(0xffffffffu, s1, 2);
            const float i0 = 1.f / s0, i1 = 1.f / s1;
            #pragma unroll
            for (int nt = 0; nt < 4; nt++) {
                float2 w0 = make_float2(l0[2*nt]*i0, l0[2*nt+1]*i0);
                float2 w1 = make_float2(l1[2*nt]*i1, l1[2*nt+1]*i1);
                *(float2*)(sWb + (g  )*WB_STR + nt*8 + 2*tig) = w0;
                *(float2*)(sWb + (g+8)*WB_STR + nt*8 + 2*tig) = w1;
            }
        }
        __syncwarp();

        // ================= G3: out[16x16] = Y[16x512] @ F^T =================
        // Y[row][q=n*16+d] = w[row][n] * diff[row][d] built in registers.
        float dgA[4], dgB[4];
        #pragma unroll
        for (int k4 = 0; k4 < 4; k4++) {
            dgA[k4] = sm[OF_DIFF + (wrb+g  )*DF_STR + k4*4 + tig];
            dgB[k4] = sm[OF_DIFF + (wrb+g+8)*DF_STR + k4*4 + tig];
        }
        float acc3[2][4];
        #pragma unroll
        for (int nt = 0; nt < 2; nt++)
            acc3[nt][0] = acc3[nt][1] = acc3[nt][2] = acc3[nt][3] = 0.f;

        #pragma unroll 4
        for (int ktp = 0; ktp < 32; ktp++) {       // n = ktp; kt = 2ktp, 2ktp+1
            const float wg  = sWb[(g  )*WB_STR + ktp];
            const float wg8 = sWb[(g+8)*WB_STR + ktp];
            const int kb = ktp * 16;               // 8*kt for kt=2ktp
            // kt even: d = tig, tig+4
            {
                uint32_t a0 = tf32u(wg  * dgA[0]);
                uint32_t a1 = tf32u(wg8 * dgB[0]);
                uint32_t a2 = tf32u(wg  * dgA[1]);
                uint32_t a3 = tf32u(wg8 * dgB[1]);
                #pragma unroll
                for (int nt = 0; nt < 2; nt++) {
                    uint32_t b0 = smu[OF_F + (nt*8+g)*F_STR + kb + tig];
                    uint32_t b1v = smu[OF_F + (nt*8+g)*F_STR + kb + tig + 4];
                    mma8(acc3[nt][0], acc3[nt][1], acc3[nt][2], acc3[nt][3],
                         a0, a1, a2, a3, b0, b1v);
                }
            }
            // kt odd: d = tig+8, tig+12
            {
                uint32_t a0 = tf32u(wg  * dgA[2]);
                uint32_t a1 = tf32u(wg8 * dgB[2]);
                uint32_t a2 = tf32u(wg  * dgA[3]);
                uint32_t a3 = tf32u(wg8 * dgB[3]);
                #pragma unroll
                for (int nt = 0; nt < 2; nt++) {
                    uint32_t b0 = smu[OF_F + (nt*8+g)*F_STR + kb + 8 + tig];
                    uint32_t b1v = smu[OF_F + (nt*8+g)*F_STR + kb + 8 + tig + 4];
                    mma8(acc3[nt][0], acc3[nt][1], acc3[nt][2], acc3[nt][3],
                         a0, a1, a2, a3, b0, b1v);
                }
            }
        }

        // ---- store: thread holds rows g,g+8; dims {2tig,2tig+1} and {8+2tig,8+2tig+1} ----
        {
            const int row0 = tile*TMROWS + wrb + g;
            if (row0 < Btot) {
                *(float2*)(out + (size_t)row0*DD + 2*tig)     = make_float2(acc3[0][0], acc3[0][1]);
                *(float2*)(out + (size_t)row0*DD + 8 + 2*tig) = make_float2(acc3[1][0], acc3[1][1]);
            }
            const int row1 = row0 + 8;
            if (row1 < Btot) {
                *(float2*)(out + (size_t)row1*DD + 2*tig)     = make_float2(acc3[0][2], acc3[0][3]);
                *(float2*)(out + (size_t)row1*DD + 8 + 2*tig) = make_float2(acc3[1][2], acc3[1][3]);
            }
        }
        __syncthreads();   // protect sdiff before next tile overwrites it
    }
}

extern "C" void kernel_launch(void* const* d_in, const int* in_sizes, int n_in,
                              void* d_out, int out_size)
{
    const float* x_cur = (const float*)d_in[0];
    const float* W1    = (const float*)d_in[1];
    const float* b1    = (const float*)d_in[2];
    const float* W2    = (const float*)d_in[3];
    const float* b2    = (const float*)d_in[4];
    const float* Bm    = (const float*)d_in[5];
    const float* Cm    = (const float*)d_in[6];
    const float* xt    = (const float*)d_in[7];
    float* out = (float*)d_out;

    const int Btot   = in_sizes[0] / DD;
    const int ntiles = (Btot + TMROWS - 1) / TMROWS;

    cudaFuncSetAttribute(fused_gated_ds_mma,
                         cudaFuncAttributeMaxDynamicSharedMemorySize, SMEM_BYTES);

    int dev = 0, sms = 148;
    cudaGetDevice(&dev);
    cudaDeviceGetAttribute(&sms, cudaDevAttrMultiProcessorCount, dev);
    const int grid = sms < ntiles ? sms : ntiles;

    fused_gated_ds_mma<<<grid, THREADS, SMEM_BYTES>>>(
        x_cur, W1, b1, W2, b2, Bm, Cm, xt, out, Btot, ntiles);
}

// round 12
// speedup vs baseline: 3.8045x; 1.0943x over previous
#include <cuda_runtime.h>
#include <cstdint>

#define DD 16
#define NN 32
#define HH 128
#define TMROWS 256
#define THREADS 512
#define WARPS 16

// smem float-index offsets (padded strides for conflict-free fragment LDS)
#define OF_XT    0
#define OF_B2    16
#define OF_B1P   48
#define OF_W1    176
#define W1_STR   20                          /* [128][20] */
#define OF_W2    (OF_W1 + HH*W1_STR)         /* 2736 */
#define W2_STR   132                         /* [32][132] */
#define OF_F     (OF_W2 + NN*W2_STR)         /* 6960 */
#define F_STR    516                         /* [16][516] */
#define OF_DIFF  (OF_F + DD*F_STR)           /* 15216 */
#define DF_STR   20                          /* [256][20] */
#define OF_H     (OF_DIFF + TMROWS*DF_STR)   /* half-K buffer per warp [16][68] */
#define H_STR    68
#define OF_WB    (OF_H + WARPS*16*H_STR)
#define WB_STR   36                          /* per warp [16][36] */
#define SMEM_FLOATS (OF_WB + WARPS*16*WB_STR)
#define SMEM_BYTES  (SMEM_FLOATS*4)

__device__ __forceinline__ uint32_t tf32u(float x) {
    uint32_t u; asm("cvt.rna.tf32.f32 %0, %1;" : "=r"(u) : "f"(x)); return u;
}
__device__ __forceinline__ float tf32f(float x) {
    uint32_t u; asm("cvt.rna.tf32.f32 %0, %1;" : "=r"(u) : "f"(x)); return __uint_as_float(u);
}
__device__ __forceinline__ void mma8(float& c0, float& c1, float& c2, float& c3,
                                     uint32_t a0, uint32_t a1, uint32_t a2, uint32_t a3,
                                     uint32_t b0, uint32_t b1) {
    asm("mma.sync.aligned.m16n8k8.row.col.f32.tf32.tf32.f32 "
        "{%0,%1,%2,%3},{%4,%5,%6,%7},{%8,%9},{%0,%1,%2,%3};"
        : "+f"(c0), "+f"(c1), "+f"(c2), "+f"(c3)
        : "r"(a0), "r"(a1), "r"(a2), "r"(a3), "r"(b0), "r"(b1));
}

__global__ __launch_bounds__(THREADS, 1)
void fused_gated_ds_mma(
    const float* __restrict__ x_cur,
    const float* __restrict__ W1,
    const float* __restrict__ b1,
    const float* __restrict__ W2,
    const float* __restrict__ b2,
    const float* __restrict__ Bm,
    const float* __restrict__ Cm,
    const float* __restrict__ xt,
    float* __restrict__ out,
    int Btot, int ntiles)
{
    extern __shared__ float sm[];
    uint32_t* smu = (uint32_t*)sm;

    const int tid  = threadIdx.x;
    const int warp = tid >> 5;
    const int lane = tid & 31;
    const int g    = lane >> 2;   // groupID (row within m16 half)
    const int tig  = lane & 3;    // thread-in-group

    // ---- stage small vectors ----
    if (tid < DD) sm[OF_XT + tid] = xt[tid];
    if (tid < NN) sm[OF_B2 + tid] = b2[tid];
    __syncthreads();

    // ---- stage weights (once; persistent CTA) ----
    for (int i = tid; i < HH*DD; i += THREADS) {          // W1 [j][d] -> [j][20]
        int j = i >> 4, d = i & 15;
        sm[OF_W1 + j*W1_STR + d] = tf32f(W1[i]);
    }
    for (int i = tid; i < NN*HH; i += THREADS) {          // W2 [n][j] -> [n][132]
        int n = i >> 7, j = i & 127;
        sm[OF_W2 + n*W2_STR + j] = tf32f(W2[i]);
    }
    for (int i = tid; i < DD*NN*DD; i += THREADS) {       // F [k][q], q=n*16+d
        int k = i >> 9, q = i & 511;
        int n = q >> 4, d = q & 15;
        int src = n*256 + k*16 + d;
        sm[OF_F + k*F_STR + q] = tf32f(Bm[src] + Cm[src]);
    }
    if (tid < HH) {                                        // b1'[j] = b1[j] + W1 xt
        float s = b1[tid];
        #pragma unroll
        for (int d = 0; d < DD; d++) s += W1[tid*DD + d] * sm[OF_XT + d];
        sm[OF_B1P + tid] = s;
    }
    __syncthreads();

    const int wrb = warp * 16;
    float* sH  = sm + OF_H  + warp*16*H_STR;
    float* sWb = sm + OF_WB + warp*16*WB_STR;
    uint32_t* sHu = (uint32_t*)sH;

    for (int tile = blockIdx.x; tile < ntiles; tile += gridDim.x) {
        // ---- stage diff tile [256][20] (fp32): diff = xt - x ----
        {
            const int r  = tid >> 1;
            const int h8 = (tid & 1) * 8;
            const int row = tile*TMROWS + r;
            float4 d0 = make_float4(0.f,0.f,0.f,0.f), d1 = d0;
            if (row < Btot) {
                const float4* xg = (const float4*)(x_cur + (size_t)row*DD + h8);
                float4 v0 = xg[0], v1 = xg[1];
                d0.x = sm[OF_XT+h8+0] - v0.x; d0.y = sm[OF_XT+h8+1] - v0.y;
                d0.z = sm[OF_XT+h8+2] - v0.z; d0.w = sm[OF_XT+h8+3] - v0.w;
                d1.x = sm[OF_XT+h8+4] - v1.x; d1.y = sm[OF_XT+h8+5] - v1.y;
                d1.z = sm[OF_XT+h8+6] - v1.z; d1.w = sm[OF_XT+h8+7] - v1.w;
            }
            *(float4*)(sm + OF_DIFF + r*DF_STR + h8)     = d0;
            *(float4*)(sm + OF_DIFF + r*DF_STR + h8 + 4) = d1;
        }
        __syncthreads();

        // ================= G1: D1[16x128] = diff[16x16] @ W1^T =================
        uint32_t af[2][4];
        #pragma unroll
        for (int ks = 0; ks < 2; ks++) {
            af[ks][0] = tf32u(sm[OF_DIFF + (wrb+g  )*DF_STR + ks*8 + tig    ]);
            af[ks][1] = tf32u(sm[OF_DIFF + (wrb+g+8)*DF_STR + ks*8 + tig    ]);
            af[ks][2] = tf32u(sm[OF_DIFF + (wrb+g  )*DF_STR + ks*8 + tig + 4]);
            af[ks][3] = tf32u(sm[OF_DIFF + (wrb+g+8)*DF_STR + ks*8 + tig + 4]);
        }
        float acc1[16][4];
        #pragma unroll
        for (int nt = 0; nt < 16; nt++)
            acc1[nt][0] = acc1[nt][1] = acc1[nt][2] = acc1[nt][3] = 0.f;
        #pragma unroll
        for (int ks = 0; ks < 2; ks++) {
            #pragma unroll
            for (int nt = 0; nt < 16; nt++) {
                uint32_t b0 = smu[OF_W1 + (nt*8+g)*W1_STR + ks*8 + tig];
                uint32_t b1v = smu[OF_W1 + (nt*8+g)*W1_STR + ks*8 + tig + 4];
                mma8(acc1[nt][0], acc1[nt][1], acc1[nt][2], acc1[nt][3],
                     af[ks][0], af[ks][1], af[ks][2], af[ks][3], b0, b1v);
            }
        }

        // ================= G2 in two K-halves through a [16][68] buffer =========
        float acc2[4][4];
        #pragma unroll
        for (int nt = 0; nt < 4; nt++)
            acc2[nt][0] = acc2[nt][1] = acc2[nt][2] = acc2[nt][3] = 0.f;

        #pragma unroll
        for (int half = 0; half < 2; half++) {
            // H = relu(b1' - D1) for this half -> per-warp smem (tf32)
            #pragma unroll
            for (int ntl = 0; ntl < 8; ntl++) {
                const int nt = half*8 + ntl;
                const int c0 = nt*8 + 2*tig;
                const int cl = ntl*8 + 2*tig;
                float2 bb = *(float2*)(sm + OF_B1P + c0);
                float2 h0, h1;
                h0.x = tf32f(fmaxf(bb.x - acc1[nt][0], 0.f));
                h0.y = tf32f(fmaxf(bb.y - acc1[nt][1], 0.f));
                h1.x = tf32f(fmaxf(bb.x - acc1[nt][2], 0.f));
                h1.y = tf32f(fmaxf(bb.y - acc1[nt][3], 0.f));
                *(float2*)(sH + (g  )*H_STR + cl) = h0;
                *(float2*)(sH + (g+8)*H_STR + cl) = h1;
            }
            __syncwarp();

            #pragma unroll
            for (int ktl = 0; ktl < 8; ktl++) {
                const int kt = half*8 + ktl;
                uint32_t a0 = sHu[(g  )*H_STR + ktl*8 + tig];
                uint32_t a1 = sHu[(g+8)*H_STR + ktl*8 + tig];
                uint32_t a2 = sHu[(g  )*H_STR + ktl*8 + tig + 4];
                uint32_t a3 = sHu[(g+8)*H_STR + ktl*8 + tig + 4];
                #pragma unroll
                for (int nt = 0; nt < 4; nt++) {
                    uint32_t b0 = smu[OF_W2 + (nt*8+g)*W2_STR + kt*8 + tig];
                    uint32_t b1v = smu[OF_W2 + (nt*8+g)*W2_STR + kt*8 + tig + 4];
                    mma8(acc2[nt][0], acc2[nt][1], acc2[nt][2], acc2[nt][3],
                         a0, a1, a2, a3, b0, b1v);
                }
            }
            __syncwarp();
        }

        // ---- softmax (rows g and g+8; logits of a row live in one quad) ----
        {
            float l0[8], l1[8];
            #pragma unroll
            for (int nt = 0; nt < 4; nt++) {
                float2 bv = *(float2*)(sm + OF_B2 + nt*8 + 2*tig);
                l0[2*nt]   = acc2[nt][0] + bv.x;  l0[2*nt+1] = acc2[nt][1] + bv.y;
                l1[2*nt]   = acc2[nt][2] + bv.x;  l1[2*nt+1] = acc2[nt][3] + bv.y;
            }
            float m0 = l0[0], m1 = l1[0];
            #pragma unroll
            for (int i = 1; i < 8; i++) { m0 = fmaxf(m0, l0[i]); m1 = fmaxf(m1, l1[i]); }
            m0 = fmaxf(m0, __shfl_xor_sync(0xffffffffu, m0, 1));
            m0 = fmaxf(m0, __shfl_xor_sync(0xffffffffu, m0, 2));
            m1 = fmaxf(m1, __shfl_xor_sync(0xffffffffu, m1, 1));
            m1 = fmaxf(m1, __shfl_xor_sync(0xffffffffu, m1, 2));
            float s0 = 0.f, s1 = 0.f;
            #pragma unroll
            for (int i = 0; i < 8; i++) {
                l0[i] = __expf(l0[i] - m0); s0 += l0[i];
                l1[i] = __expf(l1[i] - m1); s1 += l1[i];
            }
            s0 += __shfl_xor_sync(0xffffffffu, s0, 1);
            s0 += __shfl_xor_sync(0xffffffffu, s0, 2);
            s1 += __shfl_xor_sync(0xffffffffu, s1, 1);
            s1 += __shfl_xor_sync(0xffffffffu, s1, 2);
            const float i0 = 1.f / s0, i1 = 1.f / s1;
            #pragma unroll
            for (int nt = 0; nt < 4; nt++) {
                float2 w0 = make_float2(l0[2*nt]*i0, l0[2*nt+1]*i0);
                float2 w1 = make_float2(l1[2*nt]*i1, l1[2*nt+1]*i1);
                *(float2*)(sWb + (g  )*WB_STR + nt*8 + 2*tig) = w0;
                *(float2*)(sWb + (g+8)*WB_STR + nt*8 + 2*tig) = w1;
            }
        }
        __syncwarp();

        // ================= G3: out[16x16] = Y[16x512] @ F^T =================
        // Y[row][q=n*16+d] = w[row][n] * diff[row][d] built in registers.
        float dgA[4], dgB[4];
        #pragma unroll
        for (int k4 = 0; k4 < 4; k4++) {
            dgA[k4] = sm[OF_DIFF + (wrb+g  )*DF_STR + k4*4 + tig];
            dgB[k4] = sm[OF_DIFF + (wrb+g+8)*DF_STR + k4*4 + tig];
        }
        float acc3[2][4];
        #pragma unroll
        for (int nt = 0; nt < 2; nt++)
            acc3[nt][0] = acc3[nt][1] = acc3[nt][2] = acc3[nt][3] = 0.f;

        #pragma unroll 4
        for (int ktp = 0; ktp < 32; ktp++) {       // n = ktp; kt = 2ktp, 2ktp+1
            const float wg  = sWb[(g  )*WB_STR + ktp];
            const float wg8 = sWb[(g+8)*WB_STR + ktp];
            const int kb = ktp * 16;               // 8*kt for kt=2ktp
            // kt even: d = tig, tig+4
            {
                uint32_t a0 = tf32u(wg  * dgA[0]);
                uint32_t a1 = tf32u(wg8 * dgB[0]);
                uint32_t a2 = tf32u(wg  * dgA[1]);
                uint32_t a3 = tf32u(wg8 * dgB[1]);
                #pragma unroll
                for (int nt = 0; nt < 2; nt++) {
                    uint32_t b0 = smu[OF_F + (nt*8+g)*F_STR + kb + tig];
                    uint32_t b1v = smu[OF_F + (nt*8+g)*F_STR + kb + tig + 4];
                    mma8(acc3[nt][0], acc3[nt][1], acc3[nt][2], acc3[nt][3],
                         a0, a1, a2, a3, b0, b1v);
                }
            }
            // kt odd: d = tig+8, tig+12
            {
                uint32_t a0 = tf32u(wg  * dgA[2]);
                uint32_t a1 = tf32u(wg8 * dgB[2]);
                uint32_t a2 = tf32u(wg  * dgA[3]);
                uint32_t a3 = tf32u(wg8 * dgB[3]);
                #pragma unroll
                for (int nt = 0; nt < 2; nt++) {
                    uint32_t b0 = smu[OF_F + (nt*8+g)*F_STR + kb + 8 + tig];
                    uint32_t b1v = smu[OF_F + (nt*8+g)*F_STR + kb + 8 + tig + 4];
                    mma8(acc3[nt][0], acc3[nt][1], acc3[nt][2], acc3[nt][3],
                         a0, a1, a2, a3, b0, b1v);
                }
            }
        }

        // ---- store: thread holds rows g,g+8; dims {2tig,2tig+1} and {8+2tig,8+2tig+1} ----
        {
            const int row0 = tile*TMROWS + wrb + g;
            if (row0 < Btot) {
                *(float2*)(out + (size_t)row0*DD + 2*tig)     = make_float2(acc3[0][0], acc3[0][1]);
                *(float2*)(out + (size_t)row0*DD + 8 + 2*tig) = make_float2(acc3[1][0], acc3[1][1]);
            }
            const int row1 = row0 + 8;
            if (row1 < Btot) {
                *(float2*)(out + (size_t)row1*DD + 2*tig)     = make_float2(acc3[0][2], acc3[0][3]);
                *(float2*)(out + (size_t)row1*DD + 8 + 2*tig) = make_float2(acc3[1][2], acc3[1][3]);
            }
        }
        __syncthreads();   // protect diff tile before next iteration overwrites it
    }
}

extern "C" void kernel_launch(void* const* d_in, const int* in_sizes, int n_in,
                              void* d_out, int out_size)
{
    const float* x_cur = (const float*)d_in[0];
    const float* W1    = (const float*)d_in[1];
    const float* b1    = (const float*)d_in[2];
    const float* W2    = (const float*)d_in[3];
    const float* b2    = (const float*)d_in[4];
    const float* Bm    = (const float*)d_in[5];
    const float* Cm    = (const float*)d_in[6];
    const float* xt    = (const float*)d_in[7];
    float* out = (float*)d_out;

    const int Btot   = in_sizes[0] / DD;
    const int ntiles = (Btot + TMROWS - 1) / TMROWS;

    cudaFuncSetAttribute(fused_gated_ds_mma,
                         cudaFuncAttributeMaxDynamicSharedMemorySize, SMEM_BYTES);

    int dev = 0, sms = 148;
    cudaGetDevice(&dev);
    cudaDeviceGetAttribute(&sms, cudaDevAttrMultiProcessorCount, dev);
    const int grid = sms < ntiles ? sms : ntiles;

    fused_gated_ds_mma<<<grid, THREADS, SMEM_BYTES>>>(
        x_cur, W1, b1, W2, b2, Bm, Cm, xt, out, Btot, ntiles);
}

// round 14
// speedup vs baseline: 4.1897x; 1.1012x over previous
#include <cuda_runtime.h>
#include <cstdint>

#define DD 16
#define NN 32
#define HH 128
#define TMROWS 256
#define THREADS 512
#define WARPS 16

// smem float-index offsets
#define OF_XT    0
#define OF_B2    16
#define OF_B1P   48
#define OF_W1    176
#define W1_STR   24                          /* [128][24] zipped */
#define OF_W2    (OF_W1 + HH*W1_STR)         /* 3248 */
#define W2_STR   136                         /* [32][136] zipped */
#define OF_F     (OF_W2 + NN*W2_STR)         /* 7600 */
#define F_STR    520                         /* [16][520] zipped */
#define OF_DIFF  (OF_F + DD*F_STR)           /* 15920 */
#define DF_STR   20                          /* [256][20] */
#define OF_H     (OF_DIFF + TMROWS*DF_STR)   /* 21040: per warp [16][68] */
#define H_STR    68
#define OF_WB    (OF_H + WARPS*16*H_STR)     /* 38448: per warp [16][36] */
#define WB_STR   36
#define SMEM_FLOATS (OF_WB + WARPS*16*WB_STR)
#define SMEM_BYTES  (SMEM_FLOATS*4)

__device__ __forceinline__ int zip8(int kk) { return ((kk & 3) << 1) | ((kk >> 2) & 1); }

__device__ __forceinline__ uint32_t tf32u(float x) {
    uint32_t u; asm("cvt.rna.tf32.f32 %0, %1;" : "=r"(u) : "f"(x)); return u;
}
__device__ __forceinline__ float tf32f(float x) {
    uint32_t u; asm("cvt.rna.tf32.f32 %0, %1;" : "=r"(u) : "f"(x)); return __uint_as_float(u);
}
__device__ __forceinline__ void mma8(float& c0, float& c1, float& c2, float& c3,
                                     uint32_t a0, uint32_t a1, uint32_t a2, uint32_t a3,
                                     uint32_t b0, uint32_t b1) {
    asm("mma.sync.aligned.m16n8k8.row.col.f32.tf32.tf32.f32 "
        "{%0,%1,%2,%3},{%4,%5,%6,%7},{%8,%9},{%0,%1,%2,%3};"
        : "+f"(c0), "+f"(c1), "+f"(c2), "+f"(c3)
        : "r"(a0), "r"(a1), "r"(a2), "r"(a3), "r"(b0), "r"(b1));
}

__global__ __launch_bounds__(THREADS, 1)
void fused_gated_ds_mma(
    const float* __restrict__ x_cur,
    const float* __restrict__ W1,
    const float* __restrict__ b1,
    const float* __restrict__ W2,
    const float* __restrict__ b2,
    const float* __restrict__ Bm,
    const float* __restrict__ Cm,
    const float* __restrict__ xt,
    float* __restrict__ out,
    int Btot, int ntiles)
{
    extern __shared__ float sm[];
    uint32_t* smu = (uint32_t*)sm;

    const int tid  = threadIdx.x;
    const int warp = tid >> 5;
    const int lane = tid & 31;
    const int g    = lane >> 2;   // groupID
    const int tig  = lane & 3;    // thread-in-group

    // ---- stage small vectors ----
    if (tid < DD) sm[OF_XT + tid] = xt[tid];
    if (tid < NN) sm[OF_B2 + tid] = b2[tid];
    __syncthreads();

    // ---- stage weights once (zipped B layouts: pair (k, k+4) adjacent) ----
    for (int i = tid; i < HH*DD; i += THREADS) {          // W1 [j][d]
        int j = i >> 4, d = i & 15;
        sm[OF_W1 + j*W1_STR + ((d >> 3) << 3) + zip8(d & 7)] = tf32f(W1[i]);
    }
    for (int i = tid; i < NN*HH; i += THREADS) {          // W2 [n][j]
        int n = i >> 7, j = i & 127;
        sm[OF_W2 + n*W2_STR + ((j >> 3) << 3) + zip8(j & 7)] = tf32f(W2[i]);
    }
    for (int i = tid; i < DD*NN*DD; i += THREADS) {       // F [k][q], q=n*16+d
        int k = i >> 9, q = i & 511;
        int n = q >> 4, d = q & 15;
        int src = n*256 + k*16 + d;
        sm[OF_F + k*F_STR + ((q >> 3) << 3) + zip8(q & 7)] = tf32f(Bm[src] + Cm[src]);
    }
    if (tid < HH) {                                        // b1'[j] = b1[j] + W1 xt
        float s = b1[tid];
        #pragma unroll
        for (int d = 0; d < DD; d++) s += W1[tid*DD + d] * sm[OF_XT + d];
        sm[OF_B1P + tid] = s;
    }
    __syncthreads();

    const int wrb = warp * 16;
    float* sD  = sm + OF_DIFF + wrb*DF_STR;     // this warp's 16-row diff slice
    float* sH  = sm + OF_H  + warp*16*H_STR;
    float* sWb = sm + OF_WB + warp*16*WB_STR;
    uint32_t* sHu = (uint32_t*)sH;

    // no CTA barriers below: each warp owns its diff/H/WB slices
    for (int tile = blockIdx.x; tile < ntiles; tile += gridDim.x) {
        // ---- per-warp diff staging: lane covers (row = lane>>1, half = lane&1) ----
        {
            const int r  = lane >> 1;
            const int h8 = (lane & 1) * 8;
            const int row = tile*TMROWS + wrb + r;
            float4 d0 = make_float4(0.f,0.f,0.f,0.f), d1 = d0;
            if (row < Btot) {
                const float4* xg = (const float4*)(x_cur + (size_t)row*DD + h8);
                float4 v0 = xg[0], v1 = xg[1];
                d0.x = sm[OF_XT+h8+0] - v0.x; d0.y = sm[OF_XT+h8+1] - v0.y;
                d0.z = sm[OF_XT+h8+2] - v0.z; d0.w = sm[OF_XT+h8+3] - v0.w;
                d1.x = sm[OF_XT+h8+4] - v1.x; d1.y = sm[OF_XT+h8+5] - v1.y;
                d1.z = sm[OF_XT+h8+6] - v1.z; d1.w = sm[OF_XT+h8+7] - v1.w;
            }
            *(float4*)(sD + r*DF_STR + h8)     = d0;
            *(float4*)(sD + r*DF_STR + h8 + 4) = d1;
        }
        __syncwarp();

        // ================= G1: D1[16x128] = diff[16x16] @ W1^T =================
        uint32_t af[2][4];
        #pragma unroll
        for (int ks = 0; ks < 2; ks++) {
            af[ks][0] = tf32u(sD[(g  )*DF_STR + ks*8 + tig    ]);
            af[ks][1] = tf32u(sD[(g+8)*DF_STR + ks*8 + tig    ]);
            af[ks][2] = tf32u(sD[(g  )*DF_STR + ks*8 + tig + 4]);
            af[ks][3] = tf32u(sD[(g+8)*DF_STR + ks*8 + tig + 4]);
        }
        float acc1[16][4];
        #pragma unroll
        for (int nt = 0; nt < 16; nt++)
            acc1[nt][0] = acc1[nt][1] = acc1[nt][2] = acc1[nt][3] = 0.f;
        #pragma unroll
        for (int ks = 0; ks < 2; ks++) {
            #pragma unroll
            for (int nt = 0; nt < 16; nt++) {
                uint2 bv = *(uint2*)(smu + OF_W1 + (nt*8+g)*W1_STR + ks*8 + 2*tig);
                mma8(acc1[nt][0], acc1[nt][1], acc1[nt][2], acc1[nt][3],
                     af[ks][0], af[ks][1], af[ks][2], af[ks][3], bv.x, bv.y);
            }
        }

        // ================= G2 in two K-halves through [16][68] buffer =========
        float acc2[4][4];
        #pragma unroll
        for (int nt = 0; nt < 4; nt++)
            acc2[nt][0] = acc2[nt][1] = acc2[nt][2] = acc2[nt][3] = 0.f;

        #pragma unroll
        for (int half = 0; half < 2; half++) {
            #pragma unroll
            for (int ntl = 0; ntl < 8; ntl++) {
                const int nt = half*8 + ntl;
                const int c0 = nt*8 + 2*tig;
                const int cl = ntl*8 + 2*tig;
                float2 bb = *(float2*)(sm + OF_B1P + c0);
                float2 h0, h1;
                h0.x = tf32f(fmaxf(bb.x - acc1[nt][0], 0.f));
                h0.y = tf32f(fmaxf(bb.y - acc1[nt][1], 0.f));
                h1.x = tf32f(fmaxf(bb.x - acc1[nt][2], 0.f));
                h1.y = tf32f(fmaxf(bb.y - acc1[nt][3], 0.f));
                *(float2*)(sH + (g  )*H_STR + cl) = h0;
                *(float2*)(sH + (g+8)*H_STR + cl) = h1;
            }
            __syncwarp();

            #pragma unroll
            for (int ktl = 0; ktl < 8; ktl++) {
                const int kt = half*8 + ktl;
                uint32_t a0 = sHu[(g  )*H_STR + ktl*8 + tig];
                uint32_t a1 = sHu[(g+8)*H_STR + ktl*8 + tig];
                uint32_t a2 = sHu[(g  )*H_STR + ktl*8 + tig + 4];
                uint32_t a3 = sHu[(g+8)*H_STR + ktl*8 + tig + 4];
                #pragma unroll
                for (int nt = 0; nt < 4; nt++) {
                    uint2 bv = *(uint2*)(smu + OF_W2 + (nt*8+g)*W2_STR + kt*8 + 2*tig);
                    mma8(acc2[nt][0], acc2[nt][1], acc2[nt][2], acc2[nt][3],
                         a0, a1, a2, a3, bv.x, bv.y);
                }
            }
            __syncwarp();
        }

        // ---- softmax (rows g, g+8; logits of a row live in one quad) ----
        {
            float l0[8], l1[8];
            #pragma unroll
            for (int nt = 0; nt < 4; nt++) {
                float2 bv = *(float2*)(sm + OF_B2 + nt*8 + 2*tig);
                l0[2*nt]   = acc2[nt][0] + bv.x;  l0[2*nt+1] = acc2[nt][1] + bv.y;
                l1[2*nt]   = acc2[nt][2] + bv.x;  l1[2*nt+1] = acc2[nt][3] + bv.y;
            }
            float m0 = l0[0], m1 = l1[0];
            #pragma unroll
            for (int i = 1; i < 8; i++) { m0 = fmaxf(m0, l0[i]); m1 = fmaxf(m1, l1[i]); }
            m0 = fmaxf(m0, __shfl_xor_sync(0xffffffffu, m0, 1));
            m0 = fmaxf(m0, __shfl_xor_sync(0xffffffffu, m0, 2));
            m1 = fmaxf(m1, __shfl_xor_sync(0xffffffffu, m1, 1));
            m1 = fmaxf(m1, __shfl_xor_sync(0xffffffffu, m1, 2));
            float s0 = 0.f, s1 = 0.f;
            #pragma unroll
            for (int i = 0; i < 8; i++) {
                l0[i] = __expf(l0[i] - m0); s0 += l0[i];
                l1[i] = __expf(l1[i] - m1); s1 += l1[i];
            }
            s0 += __shfl_xor_sync(0xffffffffu, s0, 1);
            s0 += __shfl_xor_sync(0xffffffffu, s0, 2);
            s1 += __shfl_xor_sync(0xffffffffu, s1, 1);
            s1 += __shfl_xor_sync(0xffffffffu, s1, 2);
            const float i0 = 1.f / s0, i1 = 1.f / s1;
            #pragma unroll
            for (int nt = 0; nt < 4; nt++) {
                float2 w0 = make_float2(l0[2*nt]*i0, l0[2*nt+1]*i0);
                float2 w1 = make_float2(l1[2*nt]*i1, l1[2*nt+1]*i1);
                *(float2*)(sWb + (g  )*WB_STR + nt*8 + 2*tig) = w0;
                *(float2*)(sWb + (g+8)*WB_STR + nt*8 + 2*tig) = w1;
            }
        }
        __syncwarp();

        // ================= G3: out[16x16] = Y[16x512] @ F^T =================
        float dgA[4], dgB[4];
        #pragma unroll
        for (int k4 = 0; k4 < 4; k4++) {
            dgA[k4] = sD[(g  )*DF_STR + k4*4 + tig];
            dgB[k4] = sD[(g+8)*DF_STR + k4*4 + tig];
        }
        float acc3[2][4];
        #pragma unroll
        for (int nt = 0; nt < 2; nt++)
            acc3[nt][0] = acc3[nt][1] = acc3[nt][2] = acc3[nt][3] = 0.f;

        #pragma unroll 4
        for (int ktp = 0; ktp < 32; ktp++) {       // n = ktp
            const float wg  = sWb[(g  )*WB_STR + ktp];
            const float wg8 = sWb[(g+8)*WB_STR + ktp];
            const int kb = ktp * 16;
            {
                uint32_t a0 = tf32u(wg  * dgA[0]);
                uint32_t a1 = tf32u(wg8 * dgB[0]);
                uint32_t a2 = tf32u(wg  * dgA[1]);
                uint32_t a3 = tf32u(wg8 * dgB[1]);
                #pragma unroll
                for (int nt = 0; nt < 2; nt++) {
                    uint2 bv = *(uint2*)(smu + OF_F + (nt*8+g)*F_STR + kb + 2*tig);
                    mma8(acc3[nt][0], acc3[nt][1], acc3[nt][2], acc3[nt][3],
                         a0, a1, a2, a3, bv.x, bv.y);
                }
            }
            {
                uint32_t a0 = tf32u(wg  * dgA[2]);
                uint32_t a1 = tf32u(wg8 * dgB[2]);
                uint32_t a2 = tf32u(wg  * dgA[3]);
                uint32_t a3 = tf32u(wg8 * dgB[3]);
                #pragma unroll
                for (int nt = 0; nt < 2; nt++) {
                    uint2 bv = *(uint2*)(smu + OF_F + (nt*8+g)*F_STR + kb + 8 + 2*tig);
                    mma8(acc3[nt][0], acc3[nt][1], acc3[nt][2], acc3[nt][3],
                         a0, a1, a2, a3, bv.x, bv.y);
                }
            }
        }

        // ---- store ----
        {
            const int row0 = tile*TMROWS + wrb + g;
            if (row0 < Btot) {
                *(float2*)(out + (size_t)row0*DD + 2*tig)     = make_float2(acc3[0][0], acc3[0][1]);
                *(float2*)(out + (size_t)row0*DD + 8 + 2*tig) = make_float2(acc3[1][0], acc3[1][1]);
            }
            const int row1 = row0 + 8;
            if (row1 < Btot) {
                *(float2*)(out + (size_t)row1*DD + 2*tig)     = make_float2(acc3[0][2], acc3[0][3]);
                *(float2*)(out + (size_t)row1*DD + 8 + 2*tig) = make_float2(acc3[1][2], acc3[1][3]);
            }
        }
        __syncwarp();   // protect own diff slice before next iteration
    }
}

extern "C" void kernel_launch(void* const* d_in, const int* in_sizes, int n_in,
                              void* d_out, int out_size)
{
    const float* x_cur = (const float*)d_in[0];
    const float* W1    = (const float*)d_in[1];
    const float* b1    = (const float*)d_in[2];
    const float* W2    = (const float*)d_in[3];
    const float* b2    = (const float*)d_in[4];
    const float* Bm    = (const float*)d_in[5];
    const float* Cm    = (const float*)d_in[6];
    const float* xt    = (const float*)d_in[7];
    float* out = (float*)d_out;

    const int Btot   = in_sizes[0] / DD;
    const int ntiles = (Btot + TMROWS - 1) / TMROWS;

    cudaFuncSetAttribute(fused_gated_ds_mma,
                         cudaFuncAttributeMaxDynamicSharedMemorySize, SMEM_BYTES);

    int dev = 0, sms = 148;
    cudaGetDevice(&dev);
    cudaDeviceGetAttribute(&sms, cudaDevAttrMultiProcessorCount, dev);
    const int grid = sms < ntiles ? sms : ntiles;

    fused_gated_ds_mma<<<grid, THREADS, SMEM_BYTES>>>(
        x_cur, W1, b1, W2, b2, Bm, Cm, xt, out, Btot, ntiles);
}